// round 16
// baseline (speedup 1.0000x reference)
#include <cuda_runtime.h>
#include <cuda_fp16.h>
#include <math.h>
#include <stdint.h>

#define B_  2
#define S_  4096
#define E_  512
#define H_  8
#define D_  64
#define BH_ (B_ * H_)

// fp16 scratch (single-term everywhere; q pre-scaled by 0.125*log2e)
__device__ __half gx_hi[8192*512];                       // x  [m][k]
__device__ __half gw_hi[1536*512];                       // W  [n][k]
__device__ __half gq_hi[BH_*S_*D_];
__device__ __half gk_hi[BH_*S_*D_];
__device__ __half gv_hi[BH_*S_*D_];

#define QSCALE 0.1803368801111204f   // (1/8) * log2(e)

// ---------------------------------------------------------------------------
// Helpers (non-'a' PTX: mma.sync / ldmatrix / cp.async — valid on sm_103)
// ---------------------------------------------------------------------------
__device__ __forceinline__ uint32_t smem_u32(const void* p) {
    uint32_t a;
    asm("{ .reg .u64 t; cvta.to.shared.u64 t, %1; cvt.u32.u64 %0, t; }" : "=r"(a) : "l"(p));
    return a;
}
#define SWZ(o)   ((o) ^ (((o) >> 3) & 0x70))   // 128B-row swizzle
#define SWZ64(o) ((o) ^ (((o) >> 3) & 0x30))   // 64B-row swizzle

__device__ __forceinline__ void ldsm_x4(uint32_t* r, uint32_t a) {
    asm volatile("ldmatrix.sync.aligned.m8n8.x4.shared.b16 {%0,%1,%2,%3}, [%4];"
        : "=r"(r[0]), "=r"(r[1]), "=r"(r[2]), "=r"(r[3]) : "r"(a));
}
__device__ __forceinline__ void ldsm_x4t(uint32_t* r, uint32_t a) {
    asm volatile("ldmatrix.sync.aligned.m8n8.x4.trans.shared.b16 {%0,%1,%2,%3}, [%4];"
        : "=r"(r[0]), "=r"(r[1]), "=r"(r[2]), "=r"(r[3]) : "r"(a));
}
__device__ __forceinline__ void mma16816(float* c, const uint32_t* a, uint32_t b0, uint32_t b1) {
    asm volatile("mma.sync.aligned.m16n8k16.row.col.f32.f16.f16.f32 "
        "{%0,%1,%2,%3}, {%4,%5,%6,%7}, {%8,%9}, {%0,%1,%2,%3};"
        : "+f"(c[0]), "+f"(c[1]), "+f"(c[2]), "+f"(c[3])
        : "r"(a[0]), "r"(a[1]), "r"(a[2]), "r"(a[3]), "r"(b0), "r"(b1));
}
__device__ __forceinline__ void cp16(uint32_t dst, const void* src) {
    asm volatile("cp.async.cg.shared.global [%0], [%1], 16;" :: "r"(dst), "l"(src) : "memory");
}
#define CP_COMMIT() asm volatile("cp.async.commit_group;" ::: "memory")

__device__ __forceinline__ uint32_t pk2(__half a, __half b) {
    __half2 t = __halves2half2(a, b);
    return *reinterpret_cast<uint32_t*>(&t);
}

// ---------------------------------------------------------------------------
// Split: x, W -> fp16. 16 floats per thread (4 independent LDG.128, MLP 4).
// ---------------------------------------------------------------------------
#define NX16 (8192*512/16)
#define NW16 (1536*512/16)
__global__ __launch_bounds__(256) void split_kernel(
    const float* __restrict__ x, const float* __restrict__ wq)
{
    size_t i = (size_t)blockIdx.x * 256 + threadIdx.x;
    const float* src;
    __half* dst;
    size_t j;
    if (i < NX16)             { j = i;        src = x;  dst = gx_hi; }
    else if (i < NX16 + NW16) { j = i - NX16; src = wq; dst = gw_hi; }
    else return;

    float4 f0 = ((const float4*)src)[j*4];
    float4 f1 = ((const float4*)src)[j*4+1];
    float4 f2 = ((const float4*)src)[j*4+2];
    float4 f3 = ((const float4*)src)[j*4+3];
    float f[16] = {f0.x, f0.y, f0.z, f0.w, f1.x, f1.y, f1.z, f1.w,
                   f2.x, f2.y, f2.z, f2.w, f3.x, f3.y, f3.z, f3.w};
    __half h[16];
    #pragma unroll
    for (int t = 0; t < 16; t++) h[t] = __float2half_rn(f[t]);
    ((uint4*)dst)[j*2]   = make_uint4(pk2(h[0],h[1]),  pk2(h[2],h[3]),
                                      pk2(h[4],h[5]),  pk2(h[6],h[7]));
    ((uint4*)dst)[j*2+1] = make_uint4(pk2(h[8],h[9]),  pk2(h[10],h[11]),
                                      pk2(h[12],h[13]), pk2(h[14],h[15]));
}

// ---------------------------------------------------------------------------
// QKV GEMM (pure fp16 single-term): C = xh*wh.
// CTA 128(M) x 128(N); warp grid 4(M) x 2(N) -> warp tile 32x64.
// K chunks of 32, 4-stage cp.async (exact tail waits). Stage = A 8K | B 8K.
// ---------------------------------------------------------------------------
#define QKV_STG 16384
__device__ __forceinline__ void qkv_issue(uint32_t sb, int m0, int nb, int kc,
                                          int stage, int tid)
{
    const uint32_t s = sb + (uint32_t)stage * QKV_STG;
    const int r  = tid >> 1;
    const int c0 = (tid & 1) * 2;
    const char* ah = (const char*)gx_hi + ((size_t)(m0 + r) * 512 + kc * 32) * 2;
    const char* bh = (const char*)gw_hi + ((size_t)(nb * 128 + r) * 512 + kc * 32) * 2;
    #pragma unroll
    for (int c = 0; c < 2; c++) {
        uint32_t o = SWZ64((uint32_t)(r * 64 + (c0 + c) * 16));
        int gb = (c0 + c) * 16;
        cp16(s + 0    + o, ah + gb);
        cp16(s + 8192 + o, bh + gb);
    }
}

__global__ __launch_bounds__(256, 2) void qkv_mma_kernel()
{
    extern __shared__ char smem[];
    const uint32_t sb = smem_u32(smem);
    const int tid  = threadIdx.x;
    const int lane = tid & 31;
    const int w    = tid >> 5;
    const int wm   = w >> 1;
    const int wn   = w & 1;
    const int nb = blockIdx.x;
    const int m0 = blockIdx.y * 128;

    qkv_issue(sb, m0, nb, 0, 0, tid); CP_COMMIT();
    qkv_issue(sb, m0, nb, 1, 1, tid); CP_COMMIT();
    qkv_issue(sb, m0, nb, 2, 2, tid); CP_COMMIT();

    float acc[2][8][4] = {};

    const int arow = wm * 32 + (lane & 15);
    const int akhi = (lane >> 4) * 16;
    const int brow = wn * 64 + (lane & 7);
    const int bkhi = (lane >> 3) * 16;

    for (int kc = 0; kc < 16; kc++) {
        // exact wait: pending groups = min(3, 16-kc); need chunk kc done
        if (kc <= 13)      asm volatile("cp.async.wait_group 2;" ::: "memory");
        else if (kc == 14) asm volatile("cp.async.wait_group 1;" ::: "memory");
        else               asm volatile("cp.async.wait_group 0;" ::: "memory");
        __syncthreads();
        if (kc + 3 < 16) {
            qkv_issue(sb, m0, nb, kc + 3, (kc + 3) & 3, tid);
            CP_COMMIT();
        }

        const uint32_t base = sb + (uint32_t)(kc & 3) * QKV_STG;

        uint32_t ah[2][2][4];
        #pragma unroll
        for (int mt = 0; mt < 2; mt++) {
            #pragma unroll
            for (int k16 = 0; k16 < 2; k16++) {
                uint32_t o = SWZ64((uint32_t)((arow + mt * 16) * 64 + k16 * 32 + akhi));
                ldsm_x4(ah[mt][k16], base + o);
            }
        }
        #pragma unroll
        for (int nn = 0; nn < 8; nn++) {
            uint32_t o2 = SWZ64((uint32_t)((brow + nn * 8) * 64 + bkhi));
            uint32_t bh[4];
            ldsm_x4(bh, base + 8192 + o2);
            #pragma unroll
            for (int k16 = 0; k16 < 2; k16++) {
                #pragma unroll
                for (int mt = 0; mt < 2; mt++)
                    mma16816(acc[mt][nn], ah[mt][k16], bh[k16*2], bh[k16*2+1]);
            }
        }
    }

    const int gcol  = nb * 128 + wn * 64;
    const int which = gcol >> 9;            // 0=q, 1=k, 2=v
    const int h     = (gcol >> 6) & 7;
    __half* dst = (which == 0) ? gq_hi : ((which == 1) ? gk_hi : gv_hi);
    const float sc = (which == 0) ? QSCALE : 1.0f;

    #pragma unroll
    for (int mt = 0; mt < 2; mt++) {
        #pragma unroll
        for (int half = 0; half < 2; half++) {
            int m = m0 + wm * 32 + mt * 16 + (lane >> 2) + half * 8;
            int b = m >> 12, s = m & 4095;
            size_t rbase = ((size_t)(b * H_ + h) * S_ + s) * D_ + (lane & 3) * 2;
            #pragma unroll
            for (int nn = 0; nn < 8; nn++) {
                float v0 = acc[mt][nn][half*2]   * sc;
                float v1 = acc[mt][nn][half*2+1] * sc;
                *(uint32_t*)&dst[rbase + nn * 8] =
                    pk2(__float2half_rn(v0), __float2half_rn(v1));
            }
        }
    }
}

// ---------------------------------------------------------------------------
// Attention — R9 verified optimum, byte-identical: pure fp16, log2-domain
// h2exp2 softmax, CTA = 128 threads (4 warps), warp tile 32(M) x 64(N),
// 128 q-rows/CTA, 3-stage cp.async KV (16KB/stage), Q persistent smem,
// dual-barrier loop. 2 CTAs/SM.
// ---------------------------------------------------------------------------
#define ATTN_STG 16384
#define SM_QH    49152
#define ATTN_SMEM 65536

__device__ __forceinline__ void attn_issue(uint32_t sb, int stage, int bh, int kt, int tid)
{
    const int row = tid >> 1;
    const int ch0 = (tid & 1) * 4;
    const size_t gbase = ((size_t)bh * S_ + (size_t)kt * 64 + row) * 64;
    const char* kh = (const char*)(gk_hi + gbase);
    const char* vh = (const char*)(gv_hi + gbase);
    const uint32_t s = sb + (uint32_t)stage * ATTN_STG;
    #pragma unroll
    for (int c = 0; c < 4; c++) {
        uint32_t o = SWZ((uint32_t)(row * 128 + (ch0 + c) * 16));
        int gb = (ch0 + c) * 16;
        cp16(s + 0    + o, kh + gb);
        cp16(s + 8192 + o, vh + gb);
    }
}

__global__ __launch_bounds__(128, 2) void attn_mma_kernel(float* __restrict__ out)
{
    extern __shared__ char smem[];
    const uint32_t sb = smem_u32(smem);
    const int tid  = threadIdx.x;
    const int lane = tid & 31;
    const int w    = tid >> 5;
    const int bh = blockIdx.y;
    const int q0 = blockIdx.x * 128;

    attn_issue(sb, 0, bh, 0, tid);
    CP_COMMIT();

    // Stage Q (128 rows x 128B): one row per thread.
    {
        const uint4* qh = (const uint4*)(gq_hi + ((size_t)bh * S_ + q0) * 64);
        #pragma unroll
        for (int c = 0; c < 8; c++) {
            uint32_t o = SWZ((uint32_t)(tid * 128 + c * 16));
            *(uint4*)(smem + SM_QH + o) = qh[tid * 8 + c];
        }
    }

    attn_issue(sb, 1, bh, 1, tid);
    CP_COMMIT();
    __syncthreads();

    float o_[2][8][4] = {};
    float lsum[2][2] = {};
    const int qrl = (lane & 7) + ((lane >> 3) & 1) * 8;

    for (int kt = 0; kt < S_ / 64; kt++) {
        asm volatile("cp.async.wait_group 1;" ::: "memory");
        __syncthreads();
        if (kt + 2 < S_ / 64) {
            attn_issue(sb, (kt + 2) % 3, bh, kt + 2, tid);
            CP_COMMIT();
        }

        const uint32_t base = sb + (uint32_t)(kt % 3) * ATTN_STG;

        // ---- S = Q K^T (log2-domain scores)
        float sacc[2][8][4] = {};
        #pragma unroll
        for (int tp = 0; tp < 2; tp++) {
            uint32_t qh2[2][2][4];
            #pragma unroll
            for (int mt = 0; mt < 2; mt++) {
                int qrow = w * 32 + mt * 16 + qrl;
                #pragma unroll
                for (int hf = 0; hf < 2; hf++) {
                    int t = tp * 2 + hf;
                    uint32_t o = SWZ((uint32_t)(qrow * 128 + t * 32 + (lane >> 4) * 16));
                    ldsm_x4(qh2[mt][hf], sb + SM_QH + o);
                }
            }
            #pragma unroll
            for (int nn = 0; nn < 8; nn++) {
                uint32_t off = SWZ((uint32_t)((nn * 8 + (lane & 7)) * 128 + tp * 64 + ((lane >> 3) << 4)));
                uint32_t kh[4];
                ldsm_x4(kh, base + off);
                #pragma unroll
                for (int hf = 0; hf < 2; hf++) {
                    #pragma unroll
                    for (int mt = 0; mt < 2; mt++)
                        mma16816(sacc[mt][nn], qh2[mt][hf], kh[hf*2], kh[hf*2+1]);
                }
            }
        }

        // ---- softmax: P = 2^s via h2exp2 (packed f16x2 = MMA A-frag)
        uint32_t ah[2][4][4];
        #pragma unroll
        for (int mt = 0; mt < 2; mt++) {
            __half2 s01 = __float2half2_rn(0.f), s23 = __float2half2_rn(0.f);
            #pragma unroll
            for (int nn = 0; nn < 8; nn++) {
                __half2 p01 = h2exp2(__floats2half2_rn(sacc[mt][nn][0], sacc[mt][nn][1]));
                __half2 p23 = h2exp2(__floats2half2_rn(sacc[mt][nn][2], sacc[mt][nn][3]));
                s01 = __hadd2(s01, p01);
                s23 = __hadd2(s23, p23);
                uint32_t q01 = *(uint32_t*)&p01, q23 = *(uint32_t*)&p23;
                int t = nn >> 1;
                if ((nn & 1) == 0) { ah[mt][t][0] = q01; ah[mt][t][1] = q23; }
                else               { ah[mt][t][2] = q01; ah[mt][t][3] = q23; }
            }
            lsum[mt][0] += __low2float(s01) + __high2float(s01);
            lsum[mt][1] += __low2float(s23) + __high2float(s23);
        }

        // ---- O += P V
        #pragma unroll
        for (int nn = 0; nn < 8; nn++) {
            #pragma unroll
            for (int tp = 0; tp < 2; tp++) {
                uint32_t off = SWZ((uint32_t)((tp * 32 + ((lane >> 3) << 3) + (lane & 7)) * 128 + nn * 16));
                uint32_t vh[4];
                ldsm_x4t(vh, base + 8192 + off);
                #pragma unroll
                for (int hf = 0; hf < 2; hf++) {
                    int t = tp * 2 + hf;
                    #pragma unroll
                    for (int mt = 0; mt < 2; mt++)
                        mma16816(o_[mt][nn], ah[mt][t], vh[hf*2], vh[hf*2+1]);
                }
            }
        }
        __syncthreads();
    }

    // ---- epilogue
    const int b = bh >> 3, h = bh & 7;
    #pragma unroll
    for (int mt = 0; mt < 2; mt++) {
        float s0 = lsum[mt][0], s1 = lsum[mt][1];
        s0 += __shfl_xor_sync(0xffffffffu, s0, 1);
        s0 += __shfl_xor_sync(0xffffffffu, s0, 2);
        s1 += __shfl_xor_sync(0xffffffffu, s1, 1);
        s1 += __shfl_xor_sync(0xffffffffu, s1, 2);
        const float i0 = 1.0f / s0, i1 = 1.0f / s1;
        const int r0 = q0 + w * 32 + mt * 16 + (lane >> 2);
        float* d0 = out + ((size_t)(b * S_ + r0)) * E_ + h * 64 + (lane & 3) * 2;
        float* d1 = d0 + (size_t)8 * E_;
        #pragma unroll
        for (int nn = 0; nn < 8; nn++) {
            *(float2*)(d0 + nn * 8) = make_float2(o_[mt][nn][0] * i0, o_[mt][nn][1] * i0);
            *(float2*)(d1 + nn * 8) = make_float2(o_[mt][nn][2] * i1, o_[mt][nn][3] * i1);
        }
    }
}

extern "C" void kernel_launch(void* const* d_in, const int* in_sizes, int n_in,
                              void* d_out, int out_size)
{
    const float* x = (const float*)d_in[0];
    const float* wq = (const float*)d_in[1];
    float* out = (float*)d_out;

    cudaFuncSetAttribute(qkv_mma_kernel,
                         cudaFuncAttributeMaxDynamicSharedMemorySize, 4 * QKV_STG);
    cudaFuncSetAttribute(attn_mma_kernel,
                         cudaFuncAttributeMaxDynamicSharedMemorySize, ATTN_SMEM);

    split_kernel<<<(NX16 + NW16 + 255) / 256, 256>>>(x, wq);
    qkv_mma_kernel<<<dim3(12, 64), 256, 4 * QKV_STG>>>();
    attn_mma_kernel<<<dim3(S_ / 128, BH_), 128, ATTN_SMEM>>>(out);
}

// round 17
// speedup vs baseline: 1.0433x; 1.0433x over previous
#include <cuda_runtime.h>
#include <cuda_fp16.h>
#include <math.h>
#include <stdint.h>

#define B_  2
#define S_  4096
#define E_  512
#define H_  8
#define D_  64
#define BH_ (B_ * H_)

// fp16 scratch (single-term everywhere; q pre-scaled by 0.125*log2e)
__device__ __half gx_hi[8192*512];                       // x  [m][k]
__device__ __half gw_hi[1536*512];                       // W  [n][k]
__device__ __half gq_hi[BH_*S_*D_];
__device__ __half gk_hi[BH_*S_*D_];
__device__ __half gv_hi[BH_*S_*D_];

#define QSCALE 0.1803368801111204f   // (1/8) * log2(e)

// ---------------------------------------------------------------------------
// Helpers (non-'a' PTX: mma.sync / ldmatrix / cp.async — valid on sm_103)
// ---------------------------------------------------------------------------
__device__ __forceinline__ uint32_t smem_u32(const void* p) {
    uint32_t a;
    asm("{ .reg .u64 t; cvta.to.shared.u64 t, %1; cvt.u32.u64 %0, t; }" : "=r"(a) : "l"(p));
    return a;
}
#define SWZ(o)   ((o) ^ (((o) >> 3) & 0x70))   // 128B-row swizzle
#define SWZ64(o) ((o) ^ (((o) >> 3) & 0x30))   // 64B-row swizzle

__device__ __forceinline__ void ldsm_x4(uint32_t* r, uint32_t a) {
    asm volatile("ldmatrix.sync.aligned.m8n8.x4.shared.b16 {%0,%1,%2,%3}, [%4];"
        : "=r"(r[0]), "=r"(r[1]), "=r"(r[2]), "=r"(r[3]) : "r"(a));
}
__device__ __forceinline__ void ldsm_x4t(uint32_t* r, uint32_t a) {
    asm volatile("ldmatrix.sync.aligned.m8n8.x4.trans.shared.b16 {%0,%1,%2,%3}, [%4];"
        : "=r"(r[0]), "=r"(r[1]), "=r"(r[2]), "=r"(r[3]) : "r"(a));
}
__device__ __forceinline__ void mma16816(float* c, const uint32_t* a, uint32_t b0, uint32_t b1) {
    asm volatile("mma.sync.aligned.m16n8k16.row.col.f32.f16.f16.f32 "
        "{%0,%1,%2,%3}, {%4,%5,%6,%7}, {%8,%9}, {%0,%1,%2,%3};"
        : "+f"(c[0]), "+f"(c[1]), "+f"(c[2]), "+f"(c[3])
        : "r"(a[0]), "r"(a[1]), "r"(a[2]), "r"(a[3]), "r"(b0), "r"(b1));
}
__device__ __forceinline__ void cp16(uint32_t dst, const void* src) {
    asm volatile("cp.async.cg.shared.global [%0], [%1], 16;" :: "r"(dst), "l"(src) : "memory");
}
#define CP_COMMIT() asm volatile("cp.async.commit_group;" ::: "memory")

__device__ __forceinline__ uint32_t pk2(__half a, __half b) {
    __half2 t = __halves2half2(a, b);
    return *reinterpret_cast<uint32_t*>(&t);
}

// ---------------------------------------------------------------------------
// Split: x, W -> fp16. 8 floats per thread.
// ---------------------------------------------------------------------------
#define NX8 (8192*512/8)
#define NW8 (1536*512/8)
__global__ __launch_bounds__(256) void split_kernel(
    const float* __restrict__ x, const float* __restrict__ wq)
{
    size_t i = (size_t)blockIdx.x * 256 + threadIdx.x;
    const float* src;
    __half* dst;
    size_t j;
    if (i < NX8)            { j = i;       src = x;  dst = gx_hi; }
    else if (i < NX8 + NW8) { j = i - NX8; src = wq; dst = gw_hi; }
    else return;

    float4 f0 = ((const float4*)src)[j*2];
    float4 f1 = ((const float4*)src)[j*2+1];
    float f[8] = {f0.x, f0.y, f0.z, f0.w, f1.x, f1.y, f1.z, f1.w};
    __half h[8];
    #pragma unroll
    for (int t = 0; t < 8; t++) h[t] = __float2half_rn(f[t]);
    ((uint4*)dst)[j] = make_uint4(pk2(h[0],h[1]), pk2(h[2],h[3]),
                                  pk2(h[4],h[5]), pk2(h[6],h[7]));
}

// ---------------------------------------------------------------------------
// QKV GEMM (pure fp16 single-term): C = xh*wh.
// CTA 128(M) x 128(N); warp grid 4(M) x 2(N) -> warp tile 32x64.
// K chunks of 32, 3-stage cp.async. Stage = A 8K | B 8K = 16K.
// ---------------------------------------------------------------------------
#define QKV_STG 16384
__device__ __forceinline__ void qkv_issue(uint32_t sb, int m0, int nb, int kc,
                                          int stage, int tid)
{
    const uint32_t s = sb + (uint32_t)stage * QKV_STG;
    const int r  = tid >> 1;
    const int c0 = (tid & 1) * 2;
    const char* ah = (const char*)gx_hi + ((size_t)(m0 + r) * 512 + kc * 32) * 2;
    const char* bh = (const char*)gw_hi + ((size_t)(nb * 128 + r) * 512 + kc * 32) * 2;
    #pragma unroll
    for (int c = 0; c < 2; c++) {
        uint32_t o = SWZ64((uint32_t)(r * 64 + (c0 + c) * 16));
        int gb = (c0 + c) * 16;
        cp16(s + 0    + o, ah + gb);
        cp16(s + 8192 + o, bh + gb);
    }
}

__global__ __launch_bounds__(256, 2) void qkv_mma_kernel()
{
    extern __shared__ char smem[];
    const uint32_t sb = smem_u32(smem);
    const int tid  = threadIdx.x;
    const int lane = tid & 31;
    const int w    = tid >> 5;
    const int wm   = w >> 1;
    const int wn   = w & 1;
    const int nb = blockIdx.x;
    const int m0 = blockIdx.y * 128;

    qkv_issue(sb, m0, nb, 0, 0, tid);
    CP_COMMIT();
    qkv_issue(sb, m0, nb, 1, 1, tid);
    CP_COMMIT();

    float acc[2][8][4] = {};

    const int arow = wm * 32 + (lane & 15);
    const int akhi = (lane >> 4) * 16;
    const int brow = wn * 64 + (lane & 7);
    const int bkhi = (lane >> 3) * 16;

    for (int kc = 0; kc < 16; kc++) {
        asm volatile("cp.async.wait_group 1;" ::: "memory");
        __syncthreads();
        if (kc + 2 < 16) {
            qkv_issue(sb, m0, nb, kc + 2, (kc + 2) % 3, tid);
            CP_COMMIT();
        }

        const uint32_t base = sb + (uint32_t)(kc % 3) * QKV_STG;

        uint32_t ah[2][2][4];
        #pragma unroll
        for (int mt = 0; mt < 2; mt++) {
            #pragma unroll
            for (int k16 = 0; k16 < 2; k16++) {
                uint32_t o = SWZ64((uint32_t)((arow + mt * 16) * 64 + k16 * 32 + akhi));
                ldsm_x4(ah[mt][k16], base + o);
            }
        }
        #pragma unroll
        for (int nn = 0; nn < 8; nn++) {
            uint32_t o2 = SWZ64((uint32_t)((brow + nn * 8) * 64 + bkhi));
            uint32_t bh[4];
            ldsm_x4(bh, base + 8192 + o2);
            #pragma unroll
            for (int k16 = 0; k16 < 2; k16++) {
                #pragma unroll
                for (int mt = 0; mt < 2; mt++)
                    mma16816(acc[mt][nn], ah[mt][k16], bh[k16*2], bh[k16*2+1]);
            }
        }
    }

    const int gcol  = nb * 128 + wn * 64;
    const int which = gcol >> 9;            // 0=q, 1=k, 2=v
    const int h     = (gcol >> 6) & 7;
    __half* dst = (which == 0) ? gq_hi : ((which == 1) ? gk_hi : gv_hi);
    const float sc = (which == 0) ? QSCALE : 1.0f;

    #pragma unroll
    for (int mt = 0; mt < 2; mt++) {
        #pragma unroll
        for (int half = 0; half < 2; half++) {
            int m = m0 + wm * 32 + mt * 16 + (lane >> 2) + half * 8;
            int b = m >> 12, s = m & 4095;
            size_t rbase = ((size_t)(b * H_ + h) * S_ + s) * D_ + (lane & 3) * 2;
            #pragma unroll
            for (int nn = 0; nn < 8; nn++) {
                float v0 = acc[mt][nn][half*2]   * sc;
                float v1 = acc[mt][nn][half*2+1] * sc;
                *(uint32_t*)&dst[rbase + nn * 8] =
                    pk2(__float2half_rn(v0), __float2half_rn(v1));
            }
        }
    }
}

// ---------------------------------------------------------------------------
// Attention — R9 verified optimum: pure fp16, log2-domain h2exp2 softmax,
// CTA = 128 threads (4 warps), warp tile 32(M) x 64(N), 128 q-rows/CTA,
// 3-stage cp.async KV (16KB/stage), Q persistent smem (frags re-read/tile),
// dual-barrier loop. 2 CTAs/SM.
// ---------------------------------------------------------------------------
#define ATTN_STG 16384
#define SM_QH    49152
#define ATTN_SMEM 65536

__device__ __forceinline__ void attn_issue(uint32_t sb, int stage, int bh, int kt, int tid)
{
    const int row = tid >> 1;
    const int ch0 = (tid & 1) * 4;
    const size_t gbase = ((size_t)bh * S_ + (size_t)kt * 64 + row) * 64;
    const char* kh = (const char*)(gk_hi + gbase);
    const char* vh = (const char*)(gv_hi + gbase);
    const uint32_t s = sb + (uint32_t)stage * ATTN_STG;
    #pragma unroll
    for (int c = 0; c < 4; c++) {
        uint32_t o = SWZ((uint32_t)(row * 128 + (ch0 + c) * 16));
        int gb = (ch0 + c) * 16;
        cp16(s + 0    + o, kh + gb);
        cp16(s + 8192 + o, vh + gb);
    }
}

__global__ __launch_bounds__(128, 2) void attn_mma_kernel(float* __restrict__ out)
{
    extern __shared__ char smem[];
    const uint32_t sb = smem_u32(smem);
    const int tid  = threadIdx.x;
    const int lane = tid & 31;
    const int w    = tid >> 5;
    const int bh = blockIdx.y;
    const int q0 = blockIdx.x * 128;

    attn_issue(sb, 0, bh, 0, tid);
    CP_COMMIT();

    // Stage Q (128 rows x 128B): one row per thread.
    {
        const uint4* qh = (const uint4*)(gq_hi + ((size_t)bh * S_ + q0) * 64);
        #pragma unroll
        for (int c = 0; c < 8; c++) {
            uint32_t o = SWZ((uint32_t)(tid * 128 + c * 16));
            *(uint4*)(smem + SM_QH + o) = qh[tid * 8 + c];
        }
    }

    attn_issue(sb, 1, bh, 1, tid);
    CP_COMMIT();
    __syncthreads();

    float o_[2][8][4] = {};
    float lsum[2][2] = {};
    const int qrl = (lane & 7) + ((lane >> 3) & 1) * 8;

    for (int kt = 0; kt < S_ / 64; kt++) {
        asm volatile("cp.async.wait_group 1;" ::: "memory");
        __syncthreads();
        if (kt + 2 < S_ / 64) {
            attn_issue(sb, (kt + 2) % 3, bh, kt + 2, tid);
            CP_COMMIT();
        }

        const uint32_t base = sb + (uint32_t)(kt % 3) * ATTN_STG;

        // ---- S = Q K^T (log2-domain scores)
        float sacc[2][8][4] = {};
        #pragma unroll
        for (int tp = 0; tp < 2; tp++) {
            uint32_t qh2[2][2][4];
            #pragma unroll
            for (int mt = 0; mt < 2; mt++) {
                int qrow = w * 32 + mt * 16 + qrl;
                #pragma unroll
                for (int hf = 0; hf < 2; hf++) {
                    int t = tp * 2 + hf;
                    uint32_t o = SWZ((uint32_t)(qrow * 128 + t * 32 + (lane >> 4) * 16));
                    ldsm_x4(qh2[mt][hf], sb + SM_QH + o);
                }
            }
            #pragma unroll
            for (int nn = 0; nn < 8; nn++) {
                uint32_t off = SWZ((uint32_t)((nn * 8 + (lane & 7)) * 128 + tp * 64 + ((lane >> 3) << 4)));
                uint32_t kh[4];
                ldsm_x4(kh, base + off);
                #pragma unroll
                for (int hf = 0; hf < 2; hf++) {
                    #pragma unroll
                    for (int mt = 0; mt < 2; mt++)
                        mma16816(sacc[mt][nn], qh2[mt][hf], kh[hf*2], kh[hf*2+1]);
                }
            }
        }

        // ---- softmax: P = 2^s via h2exp2 (packed f16x2 = MMA A-frag)
        uint32_t ah[2][4][4];
        #pragma unroll
        for (int mt = 0; mt < 2; mt++) {
            __half2 s01 = __float2half2_rn(0.f), s23 = __float2half2_rn(0.f);
            #pragma unroll
            for (int nn = 0; nn < 8; nn++) {
                __half2 p01 = h2exp2(__floats2half2_rn(sacc[mt][nn][0], sacc[mt][nn][1]));
                __half2 p23 = h2exp2(__floats2half2_rn(sacc[mt][nn][2], sacc[mt][nn][3]));
                s01 = __hadd2(s01, p01);
                s23 = __hadd2(s23, p23);
                uint32_t q01 = *(uint32_t*)&p01, q23 = *(uint32_t*)&p23;
                int t = nn >> 1;
                if ((nn & 1) == 0) { ah[mt][t][0] = q01; ah[mt][t][1] = q23; }
                else               { ah[mt][t][2] = q01; ah[mt][t][3] = q23; }
            }
            lsum[mt][0] += __low2float(s01) + __high2float(s01);
            lsum[mt][1] += __low2float(s23) + __high2float(s23);
        }

        // ---- O += P V
        #pragma unroll
        for (int nn = 0; nn < 8; nn++) {
            #pragma unroll
            for (int tp = 0; tp < 2; tp++) {
                uint32_t off = SWZ((uint32_t)((tp * 32 + ((lane >> 3) << 3) + (lane & 7)) * 128 + nn * 16));
                uint32_t vh[4];
                ldsm_x4t(vh, base + 8192 + off);
                #pragma unroll
                for (int hf = 0; hf < 2; hf++) {
                    int t = tp * 2 + hf;
                    #pragma unroll
                    for (int mt = 0; mt < 2; mt++)
                        mma16816(o_[mt][nn], ah[mt][t], vh[hf*2], vh[hf*2+1]);
                }
            }
        }
        __syncthreads();
    }

    // ---- epilogue
    const int b = bh >> 3, h = bh & 7;
    #pragma unroll
    for (int mt = 0; mt < 2; mt++) {
        float s0 = lsum[mt][0], s1 = lsum[mt][1];
        s0 += __shfl_xor_sync(0xffffffffu, s0, 1);
        s0 += __shfl_xor_sync(0xffffffffu, s0, 2);
        s1 += __shfl_xor_sync(0xffffffffu, s1, 1);
        s1 += __shfl_xor_sync(0xffffffffu, s1, 2);
        const float i0 = 1.0f / s0, i1 = 1.0f / s1;
        const int r0 = q0 + w * 32 + mt * 16 + (lane >> 2);
        float* d0 = out + ((size_t)(b * S_ + r0)) * E_ + h * 64 + (lane & 3) * 2;
        float* d1 = d0 + (size_t)8 * E_;
        #pragma unroll
        for (int nn = 0; nn < 8; nn++) {
            *(float2*)(d0 + nn * 8) = make_float2(o_[mt][nn][0] * i0, o_[mt][nn][1] * i0);
            *(float2*)(d1 + nn * 8) = make_float2(o_[mt][nn][2] * i1, o_[mt][nn][3] * i1);
        }
    }
}

extern "C" void kernel_launch(void* const* d_in, const int* in_sizes, int n_in,
                              void* d_out, int out_size)
{
    const float* x = (const float*)d_in[0];
    const float* wq = (const float*)d_in[1];
    float* out = (float*)d_out;

    cudaFuncSetAttribute(qkv_mma_kernel,
                         cudaFuncAttributeMaxDynamicSharedMemorySize, 3 * QKV_STG);
    cudaFuncSetAttribute(attn_mma_kernel,
                         cudaFuncAttributeMaxDynamicSharedMemorySize, ATTN_SMEM);

    split_kernel<<<(NX8 + NW8 + 255) / 256, 256>>>(x, wq);
    qkv_mma_kernel<<<dim3(12, 64), 256, 3 * QKV_STG>>>();
    attn_mma_kernel<<<dim3(S_ / 128, BH_), 128, ATTN_SMEM>>>(out);
}